// round 2
// baseline (speedup 1.0000x reference)
#include <cuda_runtime.h>
#include <math.h>

// Problem constants
#define B_N   4096
#define M_N   256
#define D_N   256
#define TAU_F       0.2f
#define INV2TAU_F   2.5f          // 1/(2*TAU)
#define LAM_F       8.0f
#define TOPO_F      0.5f
#define LEN_C_F     0.01f
#define SP_C_F      0.001f
// exp(-x/LAM) = 2^(-x * log2(e)/LAM)
#define NEIGH_LOG2  (-0.18033688011112042f)   // -1.4426950408889634/8

// ---------------- device scratch (no allocations allowed) ----------------
__device__ float g_dist[B_N * M_N];       // sqrt distances   [B, M]
__device__ float g_protosq[M_N * M_N];    // squared pairwise proto distances
__device__ float g_factor[M_N];           // 1 + TOPO*degree[m]
__device__ float g_rowp[M_N];             // per-row sum of edge_prob
__device__ float g_rowpd[M_N];            // per-row sum of edge_prob * protosq
__device__ float g_partial[B_N];          // per-data-row partial sums

// ---------------- helpers ----------------
__device__ __forceinline__ float fast_tanh(float x) {
    float y;
    asm("tanh.approx.f32 %0, %1;" : "=f"(y) : "f"(x));
    return y;
}

// fixed-order block reduction, 256 threads
__device__ __forceinline__ float block_reduce_256(float v, float* sh) {
    int t = threadIdx.x;
    sh[t] = v;
    __syncthreads();
    #pragma unroll
    for (int s = 128; s > 0; s >>= 1) {
        if (t < s) sh[t] += sh[t + s];
        __syncthreads();
    }
    float r = sh[0];
    __syncthreads();
    return r;
}

// ---------------- kernel 1: squared/sqrt pairwise distances ----------------
// Each block computes a [16 rows of A] x [all 256 W rows] tile.
// A is [nrows, 256], W is [256, 256], both row-major fp32.
template<bool DO_SQRT>
__global__ __launch_bounds__(256) void sqdist_kernel(const float* __restrict__ A,
                                                     const float* __restrict__ W) {
    float* out = DO_SQRT ? g_dist : g_protosq;

    __shared__ __align__(16) float xs[16 * 256];   // 16 KB: A tile
    __shared__ float ws[16 * 257];                 // 16.4 KB: staged W chunk, [dc][m] padded

    const int tid = threadIdx.x;
    const int r0  = blockIdx.x * 16;

    // load A tile (coalesced)
    const float* Ab = A + r0 * D_N;
    #pragma unroll
    for (int k = 0; k < 16; ++k) {
        xs[k * 256 + tid] = Ab[k * 256 + tid];
    }

    float acc[16];
    #pragma unroll
    for (int r = 0; r < 16; ++r) acc[r] = 0.0f;

    // 16 chunks of 16 d-values
    for (int c = 0; c < 16; ++c) {
        __syncthreads();
        // stage W[:, c*16 : c*16+16] transposed into ws[dc][m]
        #pragma unroll
        for (int k = 0; k < 16; ++k) {
            int idx = k * 256 + tid;
            int mm = idx >> 4;       // 0..255
            int dc = idx & 15;       // 0..15
            ws[dc * 257 + mm] = W[mm * 256 + c * 16 + dc];
        }
        __syncthreads();

        #pragma unroll
        for (int dd4 = 0; dd4 < 16; dd4 += 4) {
            float w0 = ws[(dd4 + 0) * 257 + tid];
            float w1 = ws[(dd4 + 1) * 257 + tid];
            float w2 = ws[(dd4 + 2) * 257 + tid];
            float w3 = ws[(dd4 + 3) * 257 + tid];
            int dbase = c * 16 + dd4;
            #pragma unroll
            for (int r = 0; r < 16; ++r) {
                float4 x = *(const float4*)&xs[r * 256 + dbase];
                float t;
                t = x.x - w0; acc[r] = fmaf(t, t, acc[r]);
                t = x.y - w1; acc[r] = fmaf(t, t, acc[r]);
                t = x.z - w2; acc[r] = fmaf(t, t, acc[r]);
                t = x.w - w3; acc[r] = fmaf(t, t, acc[r]);
            }
        }
    }

    #pragma unroll
    for (int r = 0; r < 16; ++r) {
        float v = acc[r];
        if (DO_SQRT) v = sqrtf(v);
        out[(r0 + r) * M_N + tid] = v;
    }
}

// ---------------- kernel 2: edge graph terms ----------------
// One block per prototype row i; 256 threads, one per j.
__global__ __launch_bounds__(256) void k_edge(const float* __restrict__ E) {
    __shared__ float red[256];
    const int i = blockIdx.x;
    const int j = threadIdx.x;

    float z = 0.5f * (E[i * M_N + j] + E[j * M_N + i]);
    float p = 0.0f;
    if (j != i) p = 1.0f / (1.0f + __expf(-z));
    float pd = p * g_protosq[i * M_N + j];

    float sp  = block_reduce_256(p, red);
    float spd = block_reduce_256(pd, red);

    if (j == 0) {
        g_rowp[i]   = sp;
        g_rowpd[i]  = spd;
        g_factor[i] = 1.0f + TOPO_F * sp / (float)(M_N - 1);
    }
}

// ---------------- kernel 3: soft-rank + neighborhood (the hot one) ----------------
// One block per data row b; thread i owns prototype i.
// soft_rank_i - 1 = sum_{j!=i} sigmoid((d_i - d_j)/TAU)
//                 = 0.5*(M-1) + 0.5 * sum_all_j tanh((d_i - d_j)/(2*TAU))
// (diagonal contributes tanh(0)=0, so no masking needed)
__global__ __launch_bounds__(256) void k_rank() {
    __shared__ __align__(16) float dsc[256];  // prescaled distances
    __shared__ float red[256];

    const int b   = blockIdx.x;
    const int tid = threadIdx.x;

    float v  = g_dist[b * M_N + tid];
    float di = v * INV2TAU_F;
    dsc[tid] = di;
    __syncthreads();

    float sum = 0.0f;
    const float4* d4 = (const float4*)dsc;
    #pragma unroll 8
    for (int jj = 0; jj < 64; ++jj) {
        float4 q = d4[jj];
        sum += fast_tanh(di - q.x);
        sum += fast_tanh(di - q.y);
        sum += fast_tanh(di - q.z);
        sum += fast_tanh(di - q.w);
    }

    float srm1  = 0.5f * (float)(M_N - 1) + 0.5f * sum;      // soft_rank - 1
    float neigh = exp2f(srm1 * NEIGH_LOG2);                   // exp(-srm1/LAM)
    float contrib = neigh * g_factor[tid] * v;

    float s = block_reduce_256(contrib, red);
    if (tid == 0) g_partial[b] = s;
}

// ---------------- kernel 4: final deterministic reduction ----------------
__global__ __launch_bounds__(256) void k_final(float* __restrict__ out) {
    __shared__ float red[256];
    const int t = threadIdx.x;

    float s = 0.0f;
    #pragma unroll
    for (int i = t; i < B_N; i += 256) s += g_partial[i];
    float data_sum = block_reduce_256(s, red);

    float sp  = block_reduce_256(g_rowp[t],  red);
    float spd = block_reduce_256(g_rowpd[t], red);

    if (t == 0) {
        float data_term = data_sum / ((float)B_N * (float)M_N);
        float wlen      = spd / (sp + 1e-8f);
        float sparsity  = sp / ((float)M_N * (float)M_N);
        out[0] = data_term + LEN_C_F * wlen + SP_C_F * sparsity;
    }
}

// ---------------- launch ----------------
extern "C" void kernel_launch(void* const* d_in, const int* in_sizes, int n_in,
                              void* d_out, int out_size) {
    const float* data = (const float*)d_in[0];   // [4096, 256]
    const float* w    = (const float*)d_in[1];   // [256, 256]
    const float* E    = (const float*)d_in[2];   // [256, 256]
    float* out = (float*)d_out;

    sqdist_kernel<true ><<<B_N / 16, 256>>>(data, w);  // data->proto sqrt distances
    sqdist_kernel<false><<<M_N / 16, 256>>>(w,    w);  // proto pairwise squared
    k_edge <<<M_N, 256>>>(E);
    k_rank <<<B_N, 256>>>();
    k_final<<<1,   256>>>(out);
}

// round 3
// speedup vs baseline: 1.0709x; 1.0709x over previous
#include <cuda_runtime.h>
#include <math.h>

// Problem constants
#define B_N   4096
#define M_N   256
#define D_N   256
#define ROWS_PB 16
#define NBLK  (B_N / ROWS_PB)     // 256 fused blocks
#define TAU_F       0.2f
#define INV2TAU_F   2.5f          // 1/(2*TAU)
#define TOPO_F      0.5f
#define LEN_C_F     0.01f
#define SP_C_F      0.001f
// exp(-x/LAM) = 2^(x * (-log2(e)/LAM)),  LAM = 8
#define NEIGH_LOG2  (-0.18033688011112042f)

// ---------------- device scratch ----------------
__device__ float g_protosq[M_N * M_N];
__device__ float g_factor[M_N];
__device__ float g_wsq[M_N];
__device__ float g_rowp[M_N];
__device__ float g_rowpd[M_N];
__device__ float g_partial[NBLK];

// ---------------- helpers ----------------
__device__ __forceinline__ float fast_tanh(float x) {
    float y;
    asm("tanh.approx.f32 %0, %1;" : "=f"(y) : "f"(x));
    return y;
}

__device__ __forceinline__ float block_reduce_256(float v, float* sh) {
    int t = threadIdx.x;
    sh[t] = v;
    __syncthreads();
    #pragma unroll
    for (int s = 128; s > 0; s >>= 1) {
        if (t < s) sh[t] += sh[t + s];
        __syncthreads();
    }
    float r = sh[0];
    __syncthreads();
    return r;
}

// ---------------- proto pairwise squared distances (small: 16 blocks) ----
__global__ __launch_bounds__(256) void sqdist_proto(const float* __restrict__ W) {
    __shared__ __align__(16) float xs[16 * 256];
    __shared__ float ws[16 * 257];

    const int tid = threadIdx.x;
    const int r0  = blockIdx.x * 16;

    const float* Ab = W + r0 * D_N;
    #pragma unroll
    for (int k = 0; k < 16; ++k) xs[k * 256 + tid] = Ab[k * 256 + tid];

    float acc[16];
    #pragma unroll
    for (int r = 0; r < 16; ++r) acc[r] = 0.0f;

    for (int c = 0; c < 16; ++c) {
        __syncthreads();
        #pragma unroll
        for (int k = 0; k < 16; ++k) {
            int idx = k * 256 + tid;
            int mm = idx >> 4, dc = idx & 15;
            ws[dc * 257 + mm] = W[mm * 256 + c * 16 + dc];
        }
        __syncthreads();
        #pragma unroll
        for (int g = 0; g < 4; ++g) {
            int dd = g * 4;
            float w0 = ws[(dd + 0) * 257 + tid];
            float w1 = ws[(dd + 1) * 257 + tid];
            float w2 = ws[(dd + 2) * 257 + tid];
            float w3 = ws[(dd + 3) * 257 + tid];
            int dbase = c * 16 + dd;
            #pragma unroll
            for (int r = 0; r < 16; ++r) {
                float4 x = *(const float4*)&xs[r * 256 + dbase];
                float t;
                t = x.x - w0; acc[r] = fmaf(t, t, acc[r]);
                t = x.y - w1; acc[r] = fmaf(t, t, acc[r]);
                t = x.z - w2; acc[r] = fmaf(t, t, acc[r]);
                t = x.w - w3; acc[r] = fmaf(t, t, acc[r]);
            }
        }
    }
    #pragma unroll
    for (int r = 0; r < 16; ++r)
        g_protosq[(r0 + r) * M_N + tid] = acc[r];
}

// ---------------- edge graph terms + W row norms ----------------
__global__ __launch_bounds__(256) void k_edge(const float* __restrict__ E,
                                              const float* __restrict__ W) {
    __shared__ float red[256];
    const int i = blockIdx.x;
    const int j = threadIdx.x;

    float wv = W[i * M_N + j];
    float z = 0.5f * (E[i * M_N + j] + E[j * M_N + i]);
    float p = 0.0f;
    if (j != i) p = 1.0f / (1.0f + __expf(-z));
    float pd = p * g_protosq[i * M_N + j];

    float sp  = block_reduce_256(p, red);
    float spd = block_reduce_256(pd, red);
    float sw  = block_reduce_256(wv * wv, red);

    if (j == 0) {
        g_rowp[i]   = sp;
        g_rowpd[i]  = spd;
        g_factor[i] = 1.0f + TOPO_F * sp / (float)(M_N - 1);
        g_wsq[i]    = sw;
    }
}

// ---------------- fused: distance GEMM + halved soft-rank ----------------
// 256 threads per block, 16 data rows per block.
// GEMM phase: acc[r] = x_r . w_tid  via shared-tiled dot products.
// Rank phase: warp w owns protos [32w, 32w+32); ring-shuffle halving.
__global__ __launch_bounds__(256) void k_fused(const float* __restrict__ A,
                                               const float* __restrict__ W) {
    // union region: GEMM {xs[0..4096), ws[4096..8208)}  /  rank {dall[0..4096), part[4096..5120)}
    __shared__ __align__(16) float sm[8208];
    __shared__ float red[256];
    __shared__ float xnorm_s[16];

    const int tid  = threadIdx.x;
    const int lane = tid & 31;
    const int w    = tid >> 5;
    const int r0   = blockIdx.x * ROWS_PB;

    float* xs   = sm;            // [16][256]
    float* ws   = sm + 4096;     // [16][257]
    float* dall = sm;            // [16][256] (aliases xs after GEMM)
    float* part = sm + 4096;     // [8 tiles][4 slots][32]

    // ---- load data tile ----
    const float* Ab = A + r0 * D_N;
    #pragma unroll
    for (int k = 0; k < 16; ++k) xs[k * 256 + tid] = Ab[k * 256 + tid];
    __syncthreads();

    // ---- x row squared norms ----
    {
        int rr = tid >> 4, seg = tid & 15;
        const float* xr = &xs[rr * 256 + seg * 16];
        float p = 0.0f;
        #pragma unroll
        for (int d = 0; d < 16; ++d) p = fmaf(xr[d], xr[d], p);
        red[tid] = p;
        __syncthreads();
        if (tid < 16) {
            float s = 0.0f;
            #pragma unroll
            for (int q = 0; q < 16; ++q) s += red[tid * 16 + q];
            xnorm_s[tid] = s;
        }
    }

    // ---- GEMM phase: acc[r] = sum_d x[r][d] * w[tid][d] ----
    float acc[16];
    #pragma unroll
    for (int r = 0; r < 16; ++r) acc[r] = 0.0f;

    for (int c = 0; c < 16; ++c) {
        __syncthreads();
        #pragma unroll
        for (int k = 0; k < 16; ++k) {
            int idx = k * 256 + tid;
            int mm = idx >> 4, dc = idx & 15;
            ws[dc * 257 + mm] = W[mm * 256 + c * 16 + dc];
        }
        __syncthreads();
        #pragma unroll
        for (int g = 0; g < 4; ++g) {
            int dd = g * 4;
            float w0 = ws[(dd + 0) * 257 + tid];
            float w1 = ws[(dd + 1) * 257 + tid];
            float w2 = ws[(dd + 2) * 257 + tid];
            float w3 = ws[(dd + 3) * 257 + tid];
            int dbase = c * 16 + dd;
            #pragma unroll
            for (int r = 0; r < 16; ++r) {
                float4 x = *(const float4*)&xs[r * 256 + dbase];
                acc[r] = fmaf(x.x, w0, acc[r]);
                acc[r] = fmaf(x.y, w1, acc[r]);
                acc[r] = fmaf(x.z, w2, acc[r]);
                acc[r] = fmaf(x.w, w3, acc[r]);
            }
        }
    }

    // ---- epilogue: distances (prescaled by 1/(2*tau)) into dall ----
    float wsq = g_wsq[tid];
    float fac = g_factor[tid];
    __syncthreads();                 // xs no longer needed; safe to alias
    #pragma unroll
    for (int r = 0; r < 16; ++r) {
        float d2 = xnorm_s[r] + wsq - 2.0f * acc[r];
        d2 = fmaxf(d2, 0.0f);
        dall[r * 256 + tid] = sqrtf(d2) * INV2TAU_F;
    }
    __syncthreads();

    // ---- rank phase ----
    float tot = 0.0f;
    const unsigned FULL = 0xffffffffu;
    const int lnext = (lane + 1) & 31;

    #pragma unroll 1
    for (int r = 0; r < ROWS_PB; ++r) {
        const float* drow = &dall[r * 256];
        float di = drow[tid];
        float si = 0.0f;

        // diagonal tile (within-warp protos), unhalved
        #pragma unroll
        for (int t = 1; t < 32; ++t)
            si += fast_tanh(di - drow[(w << 5) + ((lane + t) & 31)]);

        // off-diagonal tile pairs, halved via traveling sj accumulator
        #pragma unroll
        for (int dlt = 1; dlt <= 3; ++dlt) {
            int J = (w + dlt) & 7;
            float dj = drow[(J << 5) + lane];
            float sj = 0.0f;
            #pragma unroll
            for (int x = 0; x < 32; ++x) {
                float t = fast_tanh(di - dj);
                si += t; sj -= t;
                dj = __shfl_sync(FULL, dj, lnext);
                sj = __shfl_sync(FULL, sj, lnext);
            }
            part[((J << 2) + (dlt - 1)) * 32 + lane] = sj;
        }
        if (w < 4) {                    // delta = 4: done once per unordered tile pair
            int J = w + 4;
            float dj = drow[(J << 5) + lane];
            float sj = 0.0f;
            #pragma unroll
            for (int x = 0; x < 32; ++x) {
                float t = fast_tanh(di - dj);
                si += t; sj -= t;
                dj = __shfl_sync(FULL, dj, lnext);
                sj = __shfl_sync(FULL, sj, lnext);
            }
            part[((J << 2) + 3) * 32 + lane] = sj;
        }
        __syncthreads();

        si += part[((w << 2) + 0) * 32 + lane];
        si += part[((w << 2) + 1) * 32 + lane];
        si += part[((w << 2) + 2) * 32 + lane];
        if (w >= 4) si += part[((w << 2) + 3) * 32 + lane];
        __syncthreads();

        float srm1  = 127.5f + 0.5f * si;            // soft_rank - 1
        float neigh = exp2f(srm1 * NEIGH_LOG2);      // exp(-srm1/8)
        tot += neigh * fac * (di * (1.0f / INV2TAU_F));
    }

    float s = block_reduce_256(tot, red);
    if (tid == 0) g_partial[blockIdx.x] = s;
}

// ---------------- final deterministic reduction ----------------
__global__ __launch_bounds__(256) void k_final(float* __restrict__ out) {
    __shared__ float red[256];
    const int t = threadIdx.x;

    float data_sum = block_reduce_256(g_partial[t], red);
    float sp  = block_reduce_256(g_rowp[t],  red);
    float spd = block_reduce_256(g_rowpd[t], red);

    if (t == 0) {
        float data_term = data_sum / ((float)B_N * (float)M_N);
        float wlen      = spd / (sp + 1e-8f);
        float sparsity  = sp / ((float)M_N * (float)M_N);
        out[0] = data_term + LEN_C_F * wlen + SP_C_F * sparsity;
    }
}

// ---------------- launch ----------------
extern "C" void kernel_launch(void* const* d_in, const int* in_sizes, int n_in,
                              void* d_out, int out_size) {
    const float* data = (const float*)d_in[0];   // [4096, 256]
    const float* w    = (const float*)d_in[1];   // [256, 256]
    const float* E    = (const float*)d_in[2];   // [256, 256]
    float* out = (float*)d_out;

    sqdist_proto<<<M_N / 16, 256>>>(w);
    k_edge      <<<M_N, 256>>>(E, w);
    k_fused     <<<NBLK, 256>>>(data, w);
    k_final     <<<1, 256>>>(out);
}

// round 4
// speedup vs baseline: 1.0884x; 1.0164x over previous
#include <cuda_runtime.h>
#include <cuda_fp16.h>
#include <math.h>

// Problem constants
#define B_N   4096
#define M_N   256
#define D_N   256
#define TAU_F       0.2f
#define INV2TAU_F   2.5f          // 1/(2*TAU)
#define TOPO_F      0.5f
#define LEN_C_F     0.01f
#define SP_C_F      0.001f
#define NEIGH_LOG2  (-0.18033688011112042f)   // -log2(e)/8
#define NPAIR (B_N / 2)                       // 2048 row pairs

// ---------------- device scratch ----------------
__device__ float g_dist[B_N * M_N];       // fp32 distances [B, M]
__device__ float g_protosq[M_N * M_N];
__device__ float g_factor[M_N];
__device__ float g_wsq[M_N];
__device__ float g_rowp[M_N];
__device__ float g_rowpd[M_N];
__device__ float g_partial[NPAIR];

// ---------------- helpers ----------------
__device__ __forceinline__ unsigned h2tanh(unsigned x) {
    unsigned y;
    asm("tanh.approx.f16x2 %0, %1;" : "=r"(y) : "r"(x));
    return y;
}
__device__ __forceinline__ unsigned h2sub(unsigned a, unsigned b) {
    unsigned r;
    asm("sub.f16x2 %0, %1, %2;" : "=r"(r) : "r"(a), "r"(b));
    return r;
}
__device__ __forceinline__ unsigned h2add(unsigned a, unsigned b) {
    unsigned r;
    asm("add.f16x2 %0, %1, %2;" : "=r"(r) : "r"(a), "r"(b));
    return r;
}

__device__ __forceinline__ float block_reduce_256(float v, float* sh) {
    int t = threadIdx.x;
    sh[t] = v;
    __syncthreads();
    #pragma unroll
    for (int s = 128; s > 0; s >>= 1) {
        if (t < s) sh[t] += sh[t + s];
        __syncthreads();
    }
    float r = sh[0];
    __syncthreads();
    return r;
}

// ---------------- proto pairwise squared distances (16 blocks) ----------
__global__ __launch_bounds__(256) void sqdist_proto(const float* __restrict__ W) {
    __shared__ __align__(16) float xs[16 * 256];
    __shared__ float ws[16 * 260];

    const int tid = threadIdx.x;
    const int r0  = blockIdx.x * 16;

    const float* Ab = W + r0 * D_N;
    #pragma unroll
    for (int k = 0; k < 16; ++k) xs[k * 256 + tid] = Ab[k * 256 + tid];

    float acc[16];
    #pragma unroll
    for (int r = 0; r < 16; ++r) acc[r] = 0.0f;

    for (int c = 0; c < 16; ++c) {
        __syncthreads();
        #pragma unroll
        for (int k = 0; k < 16; ++k) {
            int mm = k * 16 + (tid >> 4), dc = tid & 15;
            ws[dc * 260 + mm] = W[mm * 256 + c * 16 + dc];
        }
        __syncthreads();
        #pragma unroll
        for (int g = 0; g < 4; ++g) {
            int dd = g * 4;
            float w0 = ws[(dd + 0) * 260 + tid];
            float w1 = ws[(dd + 1) * 260 + tid];
            float w2 = ws[(dd + 2) * 260 + tid];
            float w3 = ws[(dd + 3) * 260 + tid];
            int dbase = c * 16 + dd;
            #pragma unroll
            for (int r = 0; r < 16; ++r) {
                float4 x = *(const float4*)&xs[r * 256 + dbase];
                float t;
                t = x.x - w0; acc[r] = fmaf(t, t, acc[r]);
                t = x.y - w1; acc[r] = fmaf(t, t, acc[r]);
                t = x.z - w2; acc[r] = fmaf(t, t, acc[r]);
                t = x.w - w3; acc[r] = fmaf(t, t, acc[r]);
            }
        }
    }
    #pragma unroll
    for (int r = 0; r < 16; ++r)
        g_protosq[(r0 + r) * M_N + tid] = acc[r];
}

// ---------------- edge graph terms + W row norms ----------------
__global__ __launch_bounds__(256) void k_edge(const float* __restrict__ E,
                                              const float* __restrict__ W) {
    __shared__ float red[256];
    const int i = blockIdx.x;
    const int j = threadIdx.x;

    float wv = W[i * M_N + j];
    float z = 0.5f * (E[i * M_N + j] + E[j * M_N + i]);
    float p = 0.0f;
    if (j != i) p = 1.0f / (1.0f + __expf(-z));
    float pd = p * g_protosq[i * M_N + j];

    float sp  = block_reduce_256(p, red);
    float spd = block_reduce_256(pd, red);
    float sw  = block_reduce_256(wv * wv, red);

    if (j == 0) {
        g_rowp[i]   = sp;
        g_rowpd[i]  = spd;
        g_factor[i] = 1.0f + TOPO_F * sp / (float)(M_N - 1);
        g_wsq[i]    = sw;
    }
}

// ---------------- GEMM: distances via 4x4 register tiling ----------------
// Block: 16 data rows x 256 protos. Thread tile: 4 rows x 4 protos.
// tx = tid & 63 -> proto group, ty = tid >> 6 -> row group.
__global__ __launch_bounds__(256) void k_gemm(const float* __restrict__ A,
                                              const float* __restrict__ W) {
    __shared__ __align__(16) float xsT[256 * 20];  // [k][row(16, pad 20)]
    __shared__ __align__(16) float ws[16 * 260];   // [kc][proto(256, pad 260)]
    __shared__ float red[256];
    __shared__ float xn[16];

    const int tid = threadIdx.x;
    const int tx = tid & 63;
    const int ty = tid >> 6;
    const int r0 = blockIdx.x * 16;

    // load A tile (coalesced) into transposed smem + row norm partials
    {
        int rr = tid >> 4, c0 = tid & 15;
        const float* Ar = A + (r0 + rr) * D_N;
        float p = 0.0f;
        #pragma unroll
        for (int it = 0; it < 16; ++it) {
            float v = Ar[c0 + 16 * it];
            p = fmaf(v, v, p);
            xsT[(c0 + 16 * it) * 20 + rr] = v;
        }
        red[tid] = p;
    }
    __syncthreads();
    if (tid < 16) {
        float s = 0.0f;
        #pragma unroll
        for (int q = 0; q < 16; ++q) s += red[tid * 16 + q];
        xn[tid] = s;
    }

    float acc00=0,acc01=0,acc02=0,acc03=0;
    float acc10=0,acc11=0,acc12=0,acc13=0;
    float acc20=0,acc21=0,acc22=0,acc23=0;
    float acc30=0,acc31=0,acc32=0,acc33=0;

    for (int c = 0; c < 16; ++c) {
        __syncthreads();
        // stage W[:, c*16 : c*16+16] transposed: ws[dc][proto]
        #pragma unroll
        for (int k = 0; k < 16; ++k) {
            int mm = k * 16 + (tid >> 4), dc = tid & 15;
            ws[dc * 260 + mm] = W[mm * 256 + c * 16 + dc];
        }
        __syncthreads();
        #pragma unroll
        for (int kc = 0; kc < 16; ++kc) {
            float4 x4 = *(const float4*)&xsT[(c * 16 + kc) * 20 + ty * 4];
            float4 w4 = *(const float4*)&ws[kc * 260 + tx * 4];
            acc00 = fmaf(x4.x, w4.x, acc00); acc01 = fmaf(x4.x, w4.y, acc01);
            acc02 = fmaf(x4.x, w4.z, acc02); acc03 = fmaf(x4.x, w4.w, acc03);
            acc10 = fmaf(x4.y, w4.x, acc10); acc11 = fmaf(x4.y, w4.y, acc11);
            acc12 = fmaf(x4.y, w4.z, acc12); acc13 = fmaf(x4.y, w4.w, acc13);
            acc20 = fmaf(x4.z, w4.x, acc20); acc21 = fmaf(x4.z, w4.y, acc21);
            acc22 = fmaf(x4.z, w4.z, acc22); acc23 = fmaf(x4.z, w4.w, acc23);
            acc30 = fmaf(x4.w, w4.x, acc30); acc31 = fmaf(x4.w, w4.y, acc31);
            acc32 = fmaf(x4.w, w4.z, acc32); acc33 = fmaf(x4.w, w4.w, acc33);
        }
    }

    // epilogue: d = sqrt(max(|x|^2 + |w|^2 - 2 x.w, 0))
    float wn0 = g_wsq[tx * 4 + 0], wn1 = g_wsq[tx * 4 + 1];
    float wn2 = g_wsq[tx * 4 + 2], wn3 = g_wsq[tx * 4 + 3];
    #pragma unroll
    for (int r = 0; r < 4; ++r) {
        float xr = xn[ty * 4 + r];
        float a0, a1, a2, a3;
        if (r == 0) { a0=acc00; a1=acc01; a2=acc02; a3=acc03; }
        else if (r == 1) { a0=acc10; a1=acc11; a2=acc12; a3=acc13; }
        else if (r == 2) { a0=acc20; a1=acc21; a2=acc22; a3=acc23; }
        else { a0=acc30; a1=acc31; a2=acc32; a3=acc33; }
        float4 dv;
        dv.x = sqrtf(fmaxf(xr + wn0 - 2.0f * a0, 0.0f));
        dv.y = sqrtf(fmaxf(xr + wn1 - 2.0f * a1, 0.0f));
        dv.z = sqrtf(fmaxf(xr + wn2 - 2.0f * a2, 0.0f));
        dv.w = sqrtf(fmaxf(xr + wn3 - 2.0f * a3, 0.0f));
        *(float4*)&g_dist[(r0 + ty * 4 + r) * M_N + tx * 4] = dv;
    }
}

// ---------------- rank: fp16x2 tanh, one row-pair per block ----------------
__global__ __launch_bounds__(256) void k_rank2() {
    __shared__ __align__(16) unsigned c2[256];  // half2 centered scaled dists
    __shared__ float redx[256];
    __shared__ float redy[256];

    const int tid = threadIdx.x;
    const int p   = blockIdx.x;

    float d0 = g_dist[(2 * p + 0) * M_N + tid];
    float d1 = g_dist[(2 * p + 1) * M_N + tid];
    float fac = g_factor[tid];

    // exact fp32 row means
    redx[tid] = d0; redy[tid] = d1;
    __syncthreads();
    #pragma unroll
    for (int s = 128; s > 0; s >>= 1) {
        if (tid < s) { redx[tid] += redx[tid + s]; redy[tid] += redy[tid + s]; }
        __syncthreads();
    }
    float m0 = redx[0] * (1.0f / 256.0f);
    float m1 = redy[0] * (1.0f / 256.0f);
    __syncthreads();

    __half2 hc = __floats2half2_rn((d0 - m0) * INV2TAU_F, (d1 - m1) * INV2TAU_F);
    c2[tid] = *reinterpret_cast<unsigned*>(&hc);
    __syncthreads();

    const unsigned di2 = c2[tid];
    float sx = 0.0f, sy = 0.0f;

    const uint4* cc = (const uint4*)c2;
    #pragma unroll 8
    for (int jj = 0; jj < 64; ++jj) {
        uint4 q = cc[jj];
        unsigned t0 = h2tanh(h2sub(di2, q.x));
        unsigned t1 = h2tanh(h2sub(di2, q.y));
        unsigned t2 = h2tanh(h2sub(di2, q.z));
        unsigned t3 = h2tanh(h2sub(di2, q.w));
        unsigned s = h2add(h2add(t0, t1), h2add(t2, t3));   // |s| <= 4
        __half2 hs = *reinterpret_cast<__half2*>(&s);
        float2 f = __half22float2(hs);
        sx += f.x; sy += f.y;
    }

    float srm0 = 127.5f + 0.5f * sx;     // soft_rank - 1, row 2p
    float srm1 = 127.5f + 0.5f * sy;     // row 2p+1
    float contrib = exp2f(srm0 * NEIGH_LOG2) * fac * d0
                  + exp2f(srm1 * NEIGH_LOG2) * fac * d1;

    float s = block_reduce_256(contrib, redx);
    if (tid == 0) g_partial[p] = s;
}

// ---------------- final deterministic reduction ----------------
__global__ __launch_bounds__(256) void k_final(float* __restrict__ out) {
    __shared__ float red[256];
    const int t = threadIdx.x;

    float s = 0.0f;
    #pragma unroll
    for (int i = t; i < NPAIR; i += 256) s += g_partial[i];
    float data_sum = block_reduce_256(s, red);
    float sp  = block_reduce_256(g_rowp[t],  red);
    float spd = block_reduce_256(g_rowpd[t], red);

    if (t == 0) {
        float data_term = data_sum / ((float)B_N * (float)M_N);
        float wlen      = spd / (sp + 1e-8f);
        float sparsity  = sp / ((float)M_N * (float)M_N);
        out[0] = data_term + LEN_C_F * wlen + SP_C_F * sparsity;
    }
}

// ---------------- launch ----------------
extern "C" void kernel_launch(void* const* d_in, const int* in_sizes, int n_in,
                              void* d_out, int out_size) {
    const float* data = (const float*)d_in[0];   // [4096, 256]
    const float* w    = (const float*)d_in[1];   // [256, 256]
    const float* E    = (const float*)d_in[2];   // [256, 256]
    float* out = (float*)d_out;

    sqdist_proto<<<M_N / 16, 256>>>(w);
    k_edge      <<<M_N, 256>>>(E, w);            // also produces g_wsq for k_gemm
    k_gemm      <<<B_N / 16, 256>>>(data, w);
    k_rank2     <<<NPAIR, 256>>>();
    k_final     <<<1, 256>>>(out);
}

// round 5
// speedup vs baseline: 1.3921x; 1.2790x over previous
#include <cuda_runtime.h>
#include <cuda_fp16.h>
#include <math.h>

// Problem constants
#define B_N   4096
#define M_N   256
#define D_N   256
#define TAU_F       0.2f
#define INV2TAU_F   2.5f
#define TOPO_F      0.5f
#define LEN_C_F     0.01f
#define SP_C_F      0.001f
#define NEIGH_LOG2  (-0.18033688011112042f)   // -log2(e)/8
#define NPAIR (B_N / 2)                       // 2048 row pairs
#define FULLM 0xffffffffu

// ---------------- device scratch ----------------
__device__ float g_dist[B_N * M_N];
__device__ float g_protosq[M_N * M_N];
__device__ float g_factor[M_N];
__device__ float g_wsq[M_N];
__device__ float g_rowp[M_N];
__device__ float g_rowpd[M_N];
__device__ float g_partial[NPAIR];
__device__ int   g_ctr;

// ---------------- helpers ----------------
__device__ __forceinline__ unsigned h2tanh(unsigned x) {
    unsigned y;
    asm("tanh.approx.f16x2 %0, %1;" : "=r"(y) : "r"(x));
    return y;
}
__device__ __forceinline__ unsigned h2sub(unsigned a, unsigned b) {
    unsigned r;
    asm("sub.f16x2 %0, %1, %2;" : "=r"(r) : "r"(a), "r"(b));
    return r;
}
__device__ __forceinline__ unsigned h2add(unsigned a, unsigned b) {
    unsigned r;
    asm("add.f16x2 %0, %1, %2;" : "=r"(r) : "r"(a), "r"(b));
    return r;
}
__device__ __forceinline__ void h2acc(unsigned h2, float& a, float& b) {
    __half2 h = *reinterpret_cast<__half2*>(&h2);
    float2 f = __half22float2(h);
    a += f.x; b += f.y;
}
__device__ __forceinline__ void h2accneg(unsigned h2, float& a, float& b) {
    __half2 h = *reinterpret_cast<__half2*>(&h2);
    float2 f = __half22float2(h);
    a -= f.x; b -= f.y;
}

__device__ __forceinline__ float block_reduce_256(float v, float* sh) {
    int t = threadIdx.x;
    sh[t] = v;
    __syncthreads();
    #pragma unroll
    for (int s = 128; s > 0; s >>= 1) {
        if (t < s) sh[t] += sh[t + s];
        __syncthreads();
    }
    float r = sh[0];
    __syncthreads();
    return r;
}

// ---------------- proto pairwise squared distances (16 blocks) ----------
__global__ __launch_bounds__(256) void sqdist_proto(const float* __restrict__ W) {
    __shared__ __align__(16) float xs[16 * 256];
    __shared__ float ws[16 * 260];

    const int tid = threadIdx.x;
    const int r0  = blockIdx.x * 16;

    if (blockIdx.x == 0 && tid == 0) g_ctr = 0;   // reset last-block counter

    const float* Ab = W + r0 * D_N;
    #pragma unroll
    for (int k = 0; k < 16; ++k) xs[k * 256 + tid] = Ab[k * 256 + tid];

    float acc[16];
    #pragma unroll
    for (int r = 0; r < 16; ++r) acc[r] = 0.0f;

    for (int c = 0; c < 16; ++c) {
        __syncthreads();
        #pragma unroll
        for (int k = 0; k < 16; ++k) {
            int mm = k * 16 + (tid >> 4), dc = tid & 15;
            ws[dc * 260 + mm] = W[mm * 256 + c * 16 + dc];
        }
        __syncthreads();
        #pragma unroll
        for (int g = 0; g < 4; ++g) {
            int dd = g * 4;
            float w0 = ws[(dd + 0) * 260 + tid];
            float w1 = ws[(dd + 1) * 260 + tid];
            float w2 = ws[(dd + 2) * 260 + tid];
            float w3 = ws[(dd + 3) * 260 + tid];
            int dbase = c * 16 + dd;
            #pragma unroll
            for (int r = 0; r < 16; ++r) {
                float4 x = *(const float4*)&xs[r * 256 + dbase];
                float t;
                t = x.x - w0; acc[r] = fmaf(t, t, acc[r]);
                t = x.y - w1; acc[r] = fmaf(t, t, acc[r]);
                t = x.z - w2; acc[r] = fmaf(t, t, acc[r]);
                t = x.w - w3; acc[r] = fmaf(t, t, acc[r]);
            }
        }
    }
    #pragma unroll
    for (int r = 0; r < 16; ++r)
        g_protosq[(r0 + r) * M_N + tid] = acc[r];
}

// ---------------- edge graph terms + W row norms ----------------
__global__ __launch_bounds__(256) void k_edge(const float* __restrict__ E,
                                              const float* __restrict__ W) {
    __shared__ float red[256];
    const int i = blockIdx.x;
    const int j = threadIdx.x;

    float wv = W[i * M_N + j];
    float z = 0.5f * (E[i * M_N + j] + E[j * M_N + i]);
    float p = 0.0f;
    if (j != i) p = 1.0f / (1.0f + __expf(-z));
    float pd = p * g_protosq[i * M_N + j];

    float sp  = block_reduce_256(p, red);
    float spd = block_reduce_256(pd, red);
    float sw  = block_reduce_256(wv * wv, red);

    if (j == 0) {
        g_rowp[i]   = sp;
        g_rowpd[i]  = spd;
        g_factor[i] = 1.0f + TOPO_F * sp / (float)(M_N - 1);
        g_wsq[i]    = sw;
    }
}

// ---------------- GEMM: distances via 4x4 register tiling ----------------
__global__ __launch_bounds__(256) void k_gemm(const float* __restrict__ A,
                                              const float* __restrict__ W) {
    __shared__ __align__(16) float xsT[256 * 20];  // [k][row(16, pad 20)]
    __shared__ __align__(16) float ws[16 * 260];   // [kc][proto(256, pad 260)]
    __shared__ float red[256];
    __shared__ float xn[16];

    const int tid = threadIdx.x;
    const int tx = tid & 63;
    const int ty = tid >> 6;
    const int r0 = blockIdx.x * 16;

    {
        int rr = tid >> 4, c0 = tid & 15;
        const float* Ar = A + (r0 + rr) * D_N;
        float p = 0.0f;
        #pragma unroll
        for (int it = 0; it < 16; ++it) {
            float v = Ar[c0 + 16 * it];
            p = fmaf(v, v, p);
            xsT[(c0 + 16 * it) * 20 + rr] = v;
        }
        red[tid] = p;
    }
    __syncthreads();
    if (tid < 16) {
        float s = 0.0f;
        #pragma unroll
        for (int q = 0; q < 16; ++q) s += red[tid * 16 + q];
        xn[tid] = s;
    }

    float acc00=0,acc01=0,acc02=0,acc03=0;
    float acc10=0,acc11=0,acc12=0,acc13=0;
    float acc20=0,acc21=0,acc22=0,acc23=0;
    float acc30=0,acc31=0,acc32=0,acc33=0;

    for (int c = 0; c < 16; ++c) {
        __syncthreads();
        #pragma unroll
        for (int k = 0; k < 16; ++k) {
            int mm = k * 16 + (tid >> 4), dc = tid & 15;
            ws[dc * 260 + mm] = W[mm * 256 + c * 16 + dc];
        }
        __syncthreads();
        #pragma unroll
        for (int kc = 0; kc < 16; ++kc) {
            float4 x4 = *(const float4*)&xsT[(c * 16 + kc) * 20 + ty * 4];
            float4 w4 = *(const float4*)&ws[kc * 260 + tx * 4];
            acc00 = fmaf(x4.x, w4.x, acc00); acc01 = fmaf(x4.x, w4.y, acc01);
            acc02 = fmaf(x4.x, w4.z, acc02); acc03 = fmaf(x4.x, w4.w, acc03);
            acc10 = fmaf(x4.y, w4.x, acc10); acc11 = fmaf(x4.y, w4.y, acc11);
            acc12 = fmaf(x4.y, w4.z, acc12); acc13 = fmaf(x4.y, w4.w, acc13);
            acc20 = fmaf(x4.z, w4.x, acc20); acc21 = fmaf(x4.z, w4.y, acc21);
            acc22 = fmaf(x4.z, w4.z, acc22); acc23 = fmaf(x4.z, w4.w, acc23);
            acc30 = fmaf(x4.w, w4.x, acc30); acc31 = fmaf(x4.w, w4.y, acc31);
            acc32 = fmaf(x4.w, w4.z, acc32); acc33 = fmaf(x4.w, w4.w, acc33);
        }
    }

    float wn0 = g_wsq[tx * 4 + 0], wn1 = g_wsq[tx * 4 + 1];
    float wn2 = g_wsq[tx * 4 + 2], wn3 = g_wsq[tx * 4 + 3];
    #pragma unroll
    for (int r = 0; r < 4; ++r) {
        float xr = xn[ty * 4 + r];
        float a0, a1, a2, a3;
        if (r == 0) { a0=acc00; a1=acc01; a2=acc02; a3=acc03; }
        else if (r == 1) { a0=acc10; a1=acc11; a2=acc12; a3=acc13; }
        else if (r == 2) { a0=acc20; a1=acc21; a2=acc22; a3=acc23; }
        else { a0=acc30; a1=acc31; a2=acc32; a3=acc33; }
        float4 dv;
        dv.x = sqrtf(fmaxf(xr + wn0 - 2.0f * a0, 0.0f));
        dv.y = sqrtf(fmaxf(xr + wn1 - 2.0f * a1, 0.0f));
        dv.z = sqrtf(fmaxf(xr + wn2 - 2.0f * a2, 0.0f));
        dv.w = sqrtf(fmaxf(xr + wn3 - 2.0f * a3, 0.0f));
        *(float4*)&g_dist[(r0 + ty * 4 + r) * M_N + tx * 4] = dv;
    }
}

// ---------------- off-diagonal tile pair with antisymmetric reuse ------
__device__ __forceinline__ void tilepair(const unsigned* dup, unsigned di2, int lane,
                                         int J, int slot, float& sx, float& sy,
                                         float2* part) {
    const unsigned* tj = dup + J * 64;
    float sjx = 0.0f, sjy = 0.0f;
    #pragma unroll
    for (int kg = 0; kg < 8; ++kg) {
        unsigned sacc = 0u, racc = 0u;
        #pragma unroll
        for (int q = 0; q < 4; ++q) {
            const int k = kg * 4 + q;
            unsigned dj = tj[lane ^ k];
            unsigned t  = h2tanh(h2sub(di2, dj));
            unsigned r  = __shfl_xor_sync(FULLM, t, k);
            sacc = h2add(sacc, t);
            racc = h2add(racc, r);
        }
        h2acc(sacc, sx, sy);        // si += sum t
        h2accneg(racc, sjx, sjy);   // sj -= sum r
    }
    part[(J * 4 + slot) * 32 + lane] = make_float2(sjx, sjy);
}

// ---------------- rank: halved f16x2 tanh + fused final ----------------
__global__ __launch_bounds__(256) void k_rank2(float* __restrict__ out) {
    __shared__ __align__(16) unsigned dup[8 * 64];   // per-tile duplicated half2 dists
    __shared__ float2 part[8 * 4 * 32];
    __shared__ float redx[256];
    __shared__ float redy[256];
    __shared__ bool amLast;

    const int tid  = threadIdx.x;
    const int lane = tid & 31;
    const int w    = tid >> 5;
    const int p    = blockIdx.x;

    float d0  = g_dist[(2 * p + 0) * M_N + tid];
    float d1  = g_dist[(2 * p + 1) * M_N + tid];
    float fac = g_factor[tid];

    // exact fp32 row means (for fp16 centering)
    redx[tid] = d0; redy[tid] = d1;
    __syncthreads();
    #pragma unroll
    for (int s = 128; s > 0; s >>= 1) {
        if (tid < s) { redx[tid] += redx[tid + s]; redy[tid] += redy[tid + s]; }
        __syncthreads();
    }
    float m0 = redx[0] * (1.0f / 256.0f);
    float m1 = redy[0] * (1.0f / 256.0f);
    __syncthreads();

    __half2 hc = __floats2half2_rn((d0 - m0) * INV2TAU_F, (d1 - m1) * INV2TAU_F);
    unsigned hcu = *reinterpret_cast<unsigned*>(&hc);
    dup[w * 64 + lane]      = hcu;
    dup[w * 64 + 32 + lane] = hcu;
    __syncthreads();

    const unsigned di2 = dup[w * 64 + lane];
    float sx = 0.0f, sy = 0.0f;

    // ---- diagonal tile: rotation k=1..15 with reuse, k=16 unhalved ----
    {
        const unsigned* tw = dup + w * 64;
        unsigned sacc = 0u, racc = 0u;
        #pragma unroll
        for (int k = 1; k <= 15; ++k) {
            unsigned dj = tw[lane + k];
            unsigned t  = h2tanh(h2sub(di2, dj));
            unsigned r  = __shfl_sync(FULLM, t, (lane - k) & 31);
            sacc = h2add(sacc, t);
            racc = h2add(racc, r);
            if ((k & 3) == 0 || k == 15) {
                h2acc(sacc, sx, sy);
                h2accneg(racc, sx, sy);
                sacc = 0u; racc = 0u;
            }
        }
        unsigned dj = tw[lane + 16];
        unsigned t  = h2tanh(h2sub(di2, dj));
        h2acc(t, sx, sy);
    }

    // ---- off-diagonal tile pairs (each unordered pair once) ----
    tilepair(dup, di2, lane, (w + 1) & 7, 0, sx, sy, part);
    tilepair(dup, di2, lane, (w + 2) & 7, 1, sx, sy, part);
    tilepair(dup, di2, lane, (w + 3) & 7, 2, sx, sy, part);
    if (w < 4) tilepair(dup, di2, lane, w + 4, 3, sx, sy, part);
    __syncthreads();

    {
        float2 q0 = part[(w * 4 + 0) * 32 + lane];
        float2 q1 = part[(w * 4 + 1) * 32 + lane];
        float2 q2 = part[(w * 4 + 2) * 32 + lane];
        sx += q0.x + q1.x + q2.x;
        sy += q0.y + q1.y + q2.y;
        if (w >= 4) {
            float2 q3 = part[(w * 4 + 3) * 32 + lane];
            sx += q3.x; sy += q3.y;
        }
    }

    float srm0 = 127.5f + 0.5f * sx;
    float srm1 = 127.5f + 0.5f * sy;
    float contrib = exp2f(srm0 * NEIGH_LOG2) * fac * d0
                  + exp2f(srm1 * NEIGH_LOG2) * fac * d1;

    float s = block_reduce_256(contrib, redx);
    if (tid == 0) g_partial[p] = s;

    // ---- last block computes the final scalar ----
    if (tid == 0) {
        __threadfence();
        amLast = (atomicAdd(&g_ctr, 1) == NPAIR - 1);
    }
    __syncthreads();
    if (amLast) {
        float acc = 0.0f;
        #pragma unroll
        for (int i = tid; i < NPAIR; i += 256) acc += g_partial[i];
        float data_sum = block_reduce_256(acc, redx);
        float sp  = block_reduce_256(g_rowp[tid],  redx);
        float spd = block_reduce_256(g_rowpd[tid], redx);
        if (tid == 0) {
            float data_term = data_sum / ((float)B_N * (float)M_N);
            float wlen      = spd / (sp + 1e-8f);
            float sparsity  = sp / ((float)M_N * (float)M_N);
            out[0] = data_term + LEN_C_F * wlen + SP_C_F * sparsity;
        }
    }
}

// ---------------- launch ----------------
extern "C" void kernel_launch(void* const* d_in, const int* in_sizes, int n_in,
                              void* d_out, int out_size) {
    const float* data = (const float*)d_in[0];   // [4096, 256]
    const float* w    = (const float*)d_in[1];   // [256, 256]
    const float* E    = (const float*)d_in[2];   // [256, 256]
    float* out = (float*)d_out;

    sqdist_proto<<<M_N / 16, 256>>>(w);          // also resets g_ctr
    k_edge      <<<M_N, 256>>>(E, w);
    k_gemm      <<<B_N / 16, 256>>>(data, w);
    k_rank2     <<<NPAIR, 256>>>(out);
}